// round 11
// baseline (speedup 1.0000x reference)
#include <cuda_runtime.h>
#include <cuda_bf16.h>
#include <stdint.h>
#include <math.h>

#define BB 4
#define CC 64
#define WW 128
#define HH 128
#define KK 9
#define OCC 64
#define GG 16
#define EPSF 1e-5f
#define WH (WW*HH)

// ---- scratch (device globals; no allocation allowed) ----
__device__ float g_y[BB*KK*WW*HH];            // sampling y-coords
__device__ float g_z[BB*OCC*WW*HH];           // pre-GN conv output
__device__ float g_gsum[BB*GG];
__device__ float g_gsq [BB*GG];
// weight chunks: [(q*9+k)][p(hi/lo)][oc][24 bf16 (16 used, 48B padded rows)]
__device__ __align__(16) __nv_bfloat16 g_wq[36*2*OCC*24];

// linspace(-5, 4, 9): exact multiples of 0.125
__constant__ float c_lin[KK] = {-5.0f, -3.875f, -2.75f, -1.625f, -0.5f,
                                 0.625f, 1.75f, 2.875f, 4.0f};

static __device__ __forceinline__ uint32_t smem_u32(const void* p) {
    uint32_t a;
    asm("{ .reg .u64 t; cvta.to.shared.u64 t, %1; cvt.u32.u64 %0, t; }"
        : "=r"(a) : "l"(p));
    return a;
}

// ---- smem layout ----
#define SF_OFF  0
#define SA_OFF  57344
#define SB_OFF  (SA_OFF + 2*12288)     // 81920
#define S_TOT   (SB_OFF + 2*6144)      // 94208

#define LDSM_X4(r0,r1,r2,r3,addr) \
    asm volatile("ldmatrix.sync.aligned.m8n8.x4.shared.b16 {%0,%1,%2,%3}, [%4];" \
        : "=r"(r0), "=r"(r1), "=r"(r2), "=r"(r3) : "r"(addr))

#define MMA16816(d, a, b) \
    asm volatile("mma.sync.aligned.m16n8k16.row.col.f32.bf16.bf16.f32 " \
        "{%0,%1,%2,%3}, {%4,%5,%6,%7}, {%8,%9}, {%0,%1,%2,%3};" \
        : "+f"((d)[0]), "+f"((d)[1]), "+f"((d)[2]), "+f"((d)[3]) \
        : "r"((a)[0]), "r"((a)[1]), "r"((a)[2]), "r"((a)[3]), \
          "r"((b)[0]), "r"((b)[1]))

#define CP_ASYNC16(dst, src) \
    asm volatile("cp.async.ca.shared.global [%0], [%1], 16;" \
        :: "r"(dst), "l"(src) : "memory")
#define CP_COMMIT()  asm volatile("cp.async.commit_group;" ::: "memory")
#define CP_WAIT0()   asm volatile("cp.async.wait_group 0;" ::: "memory")

// ---------------------------------------------------------------------------
// Kernel A: fused weight prep + 3x3 offset conv + BN + tanh + cumsum.
// Blocks each handle 72 weight-split items (512*72 = 36864 total) before the
// offset work. Zeroes GN stats.
// ---------------------------------------------------------------------------
__global__ void __launch_bounds__(128) offset_kernel(
    const float* __restrict__ f,
    const float* __restrict__ ow,
    const float* __restrict__ ob,
    const float* __restrict__ bn_g,
    const float* __restrict__ bn_b,
    const float* __restrict__ bn_m,
    const float* __restrict__ bn_v,
    const float* __restrict__ cw)
{
    int tid = threadIdx.x;
    if (blockIdx.x == 0 && tid < BB*GG) {
        g_gsum[tid] = 0.f;
        g_gsq [tid] = 0.f;
    }

    // ---- fused conv-weight split (72 items per block) ----
    if (tid < 72) {
        int i = blockIdx.x * 72 + tid;           // < 36864 always (512*72)
        int k  = i / (OCC*CC);
        int oc = (i >> 6) & 63;
        int c  = i & 63;
        float v = cw[(oc*CC + c)*KK + k];
        __nv_bfloat16 hi = __float2bfloat16(v);
        __nv_bfloat16 lo = __float2bfloat16(v - __bfloat162float(hi));
        int q  = c >> 4, cl = c & 15;
        int chunk = q*KK + k;
        g_wq[((chunk*2 + 0)*OCC + oc)*24 + cl] = hi;
        g_wq[((chunk*2 + 1)*OCC + oc)*24 + cl] = lo;
    }

    __shared__ __align__(16) float sA[CC*9*12];   // [(c*9 + t)*12 + k], padded
    for (int i = tid; i < CC*9*KK; i += 128) {
        int c = i / 81, rem = i % 81, t = rem / 9, k = rem % 9;
        sA[(c*9 + t)*12 + k] = ow[(k*CC + c)*9 + t];
    }
    __syncthreads();

    int gidx = blockIdx.x * 128 + tid;
    int h = gidx % HH;
    int w = (gidx / HH) % WW;
    int b = gidx / (WW*HH);

    float acc[KK];
    #pragma unroll
    for (int k = 0; k < KK; k++) acc[k] = 0.f;

    const float* fb = f + b*CC*WH;
    #pragma unroll
    for (int r = 0; r < 3; r++) {
        int y = w + r - 1;
        if ((unsigned)y >= (unsigned)WW) continue;
        #pragma unroll
        for (int s = 0; s < 3; s++) {
            int x = h + s - 1;
            if ((unsigned)x >= (unsigned)HH) continue;
            int t = r*3 + s;
            const float* fp = fb + y*HH + x;
            #pragma unroll 4
            for (int c = 0; c < CC; c++) {
                float v = __ldg(fp + c*WH);
                const float4* wp = (const float4*)&sA[(c*9 + t)*12];
                float4 q0 = wp[0], q1 = wp[1];
                float  w8 = sA[(c*9 + t)*12 + 8];
                acc[0] += v * q0.x;  acc[1] += v * q0.y;
                acc[2] += v * q0.z;  acc[3] += v * q0.w;
                acc[4] += v * q1.x;  acc[5] += v * q1.y;
                acc[6] += v * q1.z;  acc[7] += v * q1.w;
                acc[8] += v * w8;
            }
        }
    }

    float offs[KK];
    #pragma unroll
    for (int k = 0; k < KK; k++) {
        float sc  = rsqrtf(__ldg(bn_v + k) + EPSF);
        float val = (acc[k] + __ldg(ob + k) - __ldg(bn_m + k)) * sc;
        val = val * __ldg(bn_g + k) + __ldg(bn_b + k);
        offs[k] = tanhf(val);
    }

    // center-out cumsum; endpoints k=0, k=8 stay RAW (reference quirk)
    float nw[KK];
    nw[4] = 0.f;
    nw[5] = offs[5];  nw[6] = nw[5] + offs[6];  nw[7] = nw[6] + offs[7];
    nw[3] = offs[3];  nw[2] = nw[3] + offs[2];  nw[1] = nw[2] + offs[1];
    nw[0] = offs[0];
    nw[8] = offs[8];

    #pragma unroll
    for (int k = 0; k < KK; k++)
        g_y[((b*KK + k)*WW + w)*HH + h] = (float)w + nw[k];
}

// ---------------------------------------------------------------------------
// Kernel B helpers
// ---------------------------------------------------------------------------
static __device__ __forceinline__ void stage_sf(
    float* SFp, const float* fq, int tid, int w)
{
    #pragma unroll
    for (int j = 0; j < 14; j++) {
        int idx  = tid + j*256;            // 0..3583 float4s
        int cl   = idx / 224;
        int rem  = idx % 224;
        int slot = rem >> 5;
        int x4   = rem & 31;
        int row  = w - 3 + slot;
        row = max(0, min(row, WW-1));
        float4 v = __ldg((const float4*)(fq + cl*WH + row*HH) + x4);
        *((float4*)(SFp + (cl*7 + slot)*128) + x4) = v;
    }
}

static __device__ __forceinline__ void do_gather(
    const float* SFp, int sub, int h, int w, float ys, float lin,
    uint32_t* hp, uint32_t* lp)
{
    float xs = (float)h + lin;
    int y0 = (int)floorf(ys); y0 = max(0, min(y0, WW-1));
    int y1 = min(y0 + 1, WW-1);
    int x0 = (int)floorf(xs); x0 = max(0, min(x0, HH-1));
    int x1 = min(x0 + 1, HH-1);
    float wy0 = ys - (float)y0, wy1 = (float)y1 - ys;
    float wx0 = xs - (float)x0, wx1 = (float)x1 - xs;
    float w00 = wy1*wx1, w01 = wy1*wx0, w10 = wy0*wx1, w11 = wy0*wx0;

    int s00 = (y0 - (w-3))*128 + x0;
    int s01 = s00 + (x1 - x0);
    int s10 = (y1 - (w-3))*128 + x0;
    int s11 = s10 + (x1 - x0);

    const float* base = SFp + (sub*8)*7*128;
    #pragma unroll
    for (int j = 0; j < 4; j++) {
        float a00 = base[s00], a01 = base[s01];
        float a10 = base[s10], a11 = base[s11];
        float sA0 = w00*a00 + w01*a01 + w10*a10 + w11*a11;
        base += 896;
        float b00 = base[s00], b01 = base[s01];
        float b10 = base[s10], b11 = base[s11];
        float sB0 = w00*b00 + w01*b01 + w10*b10 + w11*b11;
        base += 896;
        __nv_bfloat16 h0 = __float2bfloat16(sA0);
        __nv_bfloat16 h1 = __float2bfloat16(sB0);
        __nv_bfloat16 l0 = __float2bfloat16(sA0 - __bfloat162float(h0));
        __nv_bfloat16 l1 = __float2bfloat16(sB0 - __bfloat162float(h1));
        hp[j] = (uint32_t)__bfloat16_as_ushort(h0)
              | ((uint32_t)__bfloat16_as_ushort(h1) << 16);
        lp[j] = (uint32_t)__bfloat16_as_ushort(l0)
              | ((uint32_t)__bfloat16_as_ushort(l1) << 16);
    }
}

static __device__ __forceinline__ void cpasync_b(
    const char* gw, uint32_t sbdst, int tid, int q, int k)
{
    const char* src = gw + (q*KK + k)*6144;
    #pragma unroll
    for (int i = 0; i < 2; i++) {
        int t = tid + i*256;
        if (t < 384) CP_ASYNC16(sbdst + t*16, src + t*16);
    }
    CP_COMMIT();
}

// ---------------------------------------------------------------------------
// Kernel B: per (b,w) CTA, D[128h x 64oc] = sum_k G_k[128x64c] . W_k^T.
// Staged-row gather + HMMA, software-pipelined: gather(k+1) and SF staging
// for q+1 hide under MMA(k); A/B double-buffered one phase ahead.
// ---------------------------------------------------------------------------
__global__ void __launch_bounds__(256, 2) dsconv_mma_kernel(
    const float* __restrict__ f,
    const float* __restrict__ cb)
{
    extern __shared__ char smem[];
    float* SFp = (float*)smem;
    uint32_t sb = smem_u32(smem);
    int tid  = threadIdx.x;
    int lane = tid & 31;
    int wid  = tid >> 5;
    int w = blockIdx.x, b = blockIdx.y;

    int mrow = (wid & 3) * 32;
    int ncol = (wid >> 2) * 32;

    int h   = tid & 127;
    int sub = tid >> 7;

    float d[2][4][4];
    #pragma unroll
    for (int mt = 0; mt < 2; mt++)
        #pragma unroll
        for (int nt = 0; nt < 4; nt++)
            #pragma unroll
            for (int r = 0; r < 4; r++) d[mt][nt][r] = 0.f;

    float ysr[KK];
    #pragma unroll
    for (int k = 0; k < KK; k++)
        ysr[k] = g_y[((b*KK + k)*WW + w)*HH + h];

    const float* fb = f + b*CC*WH;
    const char* gw = (const char*)g_wq;

    uint32_t a_roff = (uint32_t)(lane & 15) * 48 + ((lane & 16) ? 16u : 0u);
    uint32_t b_roff = ((uint32_t)(lane & 7) + ((lane & 16) ? 8u : 0u)) * 48
                    + ((lane & 8) ? 16u : 0u);

    stage_sf(SFp, fb, tid, w);
    __syncthreads();

    int phase = 0;
    for (int q = 0; q < 4; q++) {
        // ---- prologue: A(q,0) + B(q,0) into buf ----
        {
            int buf = phase & 1;
            cpasync_b(gw, sb + SB_OFF + buf*6144, tid, q, 0);
            uint32_t hp[4], lp[4];
            do_gather(SFp, sub, h, w, ysr[0], c_lin[0], hp, lp);
            char* Abase = smem + SA_OFF + buf*12288;
            *(uint4*)(Abase + h*48 + sub*16)        = make_uint4(hp[0], hp[1], hp[2], hp[3]);
            *(uint4*)(Abase + 6144 + h*48 + sub*16) = make_uint4(lp[0], lp[1], lp[2], lp[3]);
            CP_WAIT0();
            __syncthreads();
        }

        for (int k = 0; k < KK; k++) {
            int buf = phase & 1, nxt = buf ^ 1;

            // ---- LDSM current phase's A/B (issue early) ----
            uint32_t abase = sb + SA_OFF + buf*12288;
            uint32_t bbase = sb + SB_OFF + buf*6144;
            uint32_t ah[2][4], al[2][4];
            #pragma unroll
            for (int mt = 0; mt < 2; mt++) {
                uint32_t ad = abase + (uint32_t)(mrow + mt*16)*48 + a_roff;
                LDSM_X4(ah[mt][0], ah[mt][1], ah[mt][2], ah[mt][3], ad);
                ad += 6144u;
                LDSM_X4(al[mt][0], al[mt][1], al[mt][2], al[mt][3], ad);
            }
            uint32_t bh[4][2], bl[4][2];
            #pragma unroll
            for (int half = 0; half < 2; half++) {
                uint32_t bd = bbase + (uint32_t)(ncol + half*16)*48 + b_roff;
                LDSM_X4(bh[half*2][0], bh[half*2][1],
                        bh[half*2+1][0], bh[half*2+1][1], bd);
                bd += 3072u;
                LDSM_X4(bl[half*2][0], bl[half*2][1],
                        bl[half*2+1][0], bl[half*2+1][1], bd);
            }

            // ---- prefetch next phase's inputs (hidden under MMA) ----
            uint32_t hp[4], lp[4];
            bool have_next = (k < 8);
            if (have_next) {
                cpasync_b(gw, sb + SB_OFF + nxt*6144, tid, q, k+1);
                do_gather(SFp, sub, h, w, ysr[k+1], c_lin[k+1], hp, lp);
            } else if (q < 3) {
                // all gathers of quarter q completed by end of phase k=7
                stage_sf(SFp, fb + (q+1)*16*WH, tid, w);
            }

            // ---- HMMA (3 products, hi/lo split) ----
            #pragma unroll
            for (int mt = 0; mt < 2; mt++)
                #pragma unroll
                for (int nt = 0; nt < 4; nt++) {
                    MMA16816(d[mt][nt], ah[mt], bh[nt]);
                    MMA16816(d[mt][nt], ah[mt], bl[nt]);
                    MMA16816(d[mt][nt], al[mt], bh[nt]);
                }

            if (have_next) {
                char* Abase = smem + SA_OFF + nxt*12288;
                *(uint4*)(Abase + h*48 + sub*16)        = make_uint4(hp[0], hp[1], hp[2], hp[3]);
                *(uint4*)(Abase + 6144 + h*48 + sub*16) = make_uint4(lp[0], lp[1], lp[2], lp[3]);
                CP_WAIT0();
            }
            __syncthreads();
            phase++;
        }
    }

    // ---- epilogue: bias + store z + fused GroupNorm partial stats ----
    int hr = lane >> 2;
    int op = (lane & 3) * 2;
    float gs[4], gq[4];
    #pragma unroll
    for (int nt = 0; nt < 4; nt++) { gs[nt] = 0.f; gq[nt] = 0.f; }

    #pragma unroll
    for (int mt = 0; mt < 2; mt++) {
        int hh = mrow + mt*16 + hr;
        #pragma unroll
        for (int nt = 0; nt < 4; nt++) {
            int oc = ncol + nt*8 + op;
            float b0 = __ldg(cb + oc), b1 = __ldg(cb + oc + 1);
            float* z0 = g_z + ((b*OCC + oc  )*WW + w)*HH;
            float* z1 = g_z + ((b*OCC + oc+1)*WW + w)*HH;
            float v0 = d[mt][nt][0] + b0;
            float v1 = d[mt][nt][1] + b1;
            float v2 = d[mt][nt][2] + b0;
            float v3 = d[mt][nt][3] + b1;
            z0[hh]     = v0;
            z1[hh]     = v1;
            z0[hh + 8] = v2;
            z1[hh + 8] = v3;
            gs[nt] += v0 + v1 + v2 + v3;
            gq[nt] += v0*v0 + v1*v1 + v2*v2 + v3*v3;
        }
    }

    #pragma unroll
    for (int nt = 0; nt < 4; nt++) {
        #pragma unroll
        for (int o = 0; o < 4; o++) {
            int m = (o == 0) ? 1 : (o == 1) ? 4 : (o == 2) ? 8 : 16;
            gs[nt] += __shfl_xor_sync(0xffffffffu, gs[nt], m);
            gq[nt] += __shfl_xor_sync(0xffffffffu, gq[nt], m);
        }
    }
    if ((lane & ~2) == 0) {
        int gpar = (lane >> 1) & 1;
        #pragma unroll
        for (int nt = 0; nt < 4; nt++) {
            int grp = b*GG + (ncol >> 2) + nt*2 + gpar;
            atomicAdd(&g_gsum[grp], gs[nt]);
            atomicAdd(&g_gsq [grp], gq[nt]);
        }
    }
}

// ---------------------------------------------------------------------------
// Kernel C: GroupNorm finalize + gamma/beta + ReLU, 2 float4 per thread
// ---------------------------------------------------------------------------
#define GN_HALF (BB*OCC*WH/8)
__global__ void __launch_bounds__(256) gn_kernel(
    const float* __restrict__ gn_g,
    const float* __restrict__ gn_b,
    float* __restrict__ out)
{
    int t = blockIdx.x * 256 + threadIdx.x;
    if (t >= GN_HALF) return;
    #pragma unroll
    for (int rep = 0; rep < 2; rep++) {
        int i4 = t + rep*GN_HALF;
        int base = i4 * 4;
        int oc = (base / WH) % OCC;
        int b  = base / (OCC*WH);
        int grp = b*GG + (oc >> 2);
        const float invn = 1.f / (float)(4*WH);
        float mu  = g_gsum[grp] * invn;
        float var = g_gsq [grp] * invn - mu*mu;
        float rs  = rsqrtf(var + EPSF);
        float sc = rs * __ldg(gn_g + oc);
        float sh = __ldg(gn_b + oc) - mu * sc;
        float4 z = ((const float4*)g_z)[i4];
        float4 o;
        o.x = fmaxf(z.x*sc + sh, 0.f);
        o.y = fmaxf(z.y*sc + sh, 0.f);
        o.z = fmaxf(z.z*sc + sh, 0.f);
        o.w = fmaxf(z.w*sc + sh, 0.f);
        ((float4*)out)[i4] = o;
    }
}

// ---------------------------------------------------------------------------
extern "C" void kernel_launch(void* const* d_in, const int* in_sizes, int n_in,
                              void* d_out, int out_size)
{
    const float* f        = (const float*)d_in[0];
    const float* offset_w = (const float*)d_in[1];
    const float* offset_b = (const float*)d_in[2];
    const float* bn_gamma = (const float*)d_in[3];
    const float* bn_beta  = (const float*)d_in[4];
    const float* bn_mean  = (const float*)d_in[5];
    const float* bn_var   = (const float*)d_in[6];
    const float* conv_w   = (const float*)d_in[7];
    const float* conv_b   = (const float*)d_in[8];
    const float* gn_gamma = (const float*)d_in[9];
    const float* gn_beta  = (const float*)d_in[10];
    float* out = (float*)d_out;

    cudaFuncSetAttribute(dsconv_mma_kernel,
                         cudaFuncAttributeMaxDynamicSharedMemorySize, S_TOT);

    offset_kernel<<<(BB*WW*HH)/128, 128>>>(f, offset_w, offset_b,
                                           bn_gamma, bn_beta, bn_mean, bn_var,
                                           conv_w);

    dim3 gridB(WW, BB);
    dsconv_mma_kernel<<<gridB, 256, S_TOT>>>(f, conv_b);

    gn_kernel<<<(GN_HALF + 255)/256, 256>>>(gn_gamma, gn_beta, out);
}

// round 12
// speedup vs baseline: 1.1279x; 1.1279x over previous
#include <cuda_runtime.h>
#include <cuda_bf16.h>
#include <stdint.h>
#include <math.h>

#define BB 4
#define CC 64
#define WW 128
#define HH 128
#define KK 9
#define OCC 64
#define GG 16
#define EPSF 1e-5f
#define WH (WW*HH)

// ---- scratch (device globals; no allocation allowed) ----
__device__ float g_y[BB*KK*WW*HH];            // sampling y-coords
__device__ float g_z[BB*OCC*WW*HH];           // pre-GN conv output
__device__ float g_gsum[BB*GG];
__device__ float g_gsq [BB*GG];
// weight chunks: [(q*9+k)][p(hi/lo)][oc][24 bf16 (16 used, 48B padded rows)]
__device__ __align__(16) __nv_bfloat16 g_wq[36*2*OCC*24];

// linspace(-5, 4, 9): exact multiples of 0.125
__constant__ float c_lin[KK] = {-5.0f, -3.875f, -2.75f, -1.625f, -0.5f,
                                 0.625f, 1.75f, 2.875f, 4.0f};

static __device__ __forceinline__ uint32_t smem_u32(const void* p) {
    uint32_t a;
    asm("{ .reg .u64 t; cvta.to.shared.u64 t, %1; cvt.u32.u64 %0, t; }"
        : "=r"(a) : "l"(p));
    return a;
}

// ---- smem layout (main kernel) ----
#define SF_OFF  0
#define SA_OFF  57344
#define SB_OFF  (SA_OFF + 2*12288)     // 81920
#define S_TOT   (SB_OFF + 2*6144)      // 94208

#define LDSM_X4(r0,r1,r2,r3,addr) \
    asm volatile("ldmatrix.sync.aligned.m8n8.x4.shared.b16 {%0,%1,%2,%3}, [%4];" \
        : "=r"(r0), "=r"(r1), "=r"(r2), "=r"(r3) : "r"(addr))

#define MMA16816(d, a, b) \
    asm volatile("mma.sync.aligned.m16n8k16.row.col.f32.bf16.bf16.f32 " \
        "{%0,%1,%2,%3}, {%4,%5,%6,%7}, {%8,%9}, {%0,%1,%2,%3};" \
        : "+f"((d)[0]), "+f"((d)[1]), "+f"((d)[2]), "+f"((d)[3]) \
        : "r"((a)[0]), "r"((a)[1]), "r"((a)[2]), "r"((a)[3]), \
          "r"((b)[0]), "r"((b)[1]))

#define CP_ASYNC16(dst, src) \
    asm volatile("cp.async.ca.shared.global [%0], [%1], 16;" \
        :: "r"(dst), "l"(src) : "memory")
#define CP_COMMIT()  asm volatile("cp.async.commit_group;" ::: "memory")
#define CP_WAIT0()   asm volatile("cp.async.wait_group 0;" ::: "memory")

// ---------------------------------------------------------------------------
// Kernel A: fused weight prep + 3x3 offset conv + BN + tanh + cumsum.
// 512 threads per block: 128 pixels x 4 channel-slices of 16. Partial sums
// combined via padded smem (stride 13 -> conflict-free). Zeroes GN stats.
// ---------------------------------------------------------------------------
__global__ void __launch_bounds__(512) offset_kernel(
    const float* __restrict__ f,
    const float* __restrict__ ow,
    const float* __restrict__ ob,
    const float* __restrict__ bn_g,
    const float* __restrict__ bn_b,
    const float* __restrict__ bn_m,
    const float* __restrict__ bn_v,
    const float* __restrict__ cw)
{
    int tid = threadIdx.x;
    if (blockIdx.x == 0 && tid < BB*GG) {
        g_gsum[tid] = 0.f;
        g_gsq [tid] = 0.f;
    }

    // ---- fused conv-weight split (72 items per block; 512*72 = 36864) ----
    if (tid < 72) {
        int i = blockIdx.x * 72 + tid;
        int k  = i / (OCC*CC);
        int oc = (i >> 6) & 63;
        int c  = i & 63;
        float v = cw[(oc*CC + c)*KK + k];
        __nv_bfloat16 hi = __float2bfloat16(v);
        __nv_bfloat16 lo = __float2bfloat16(v - __bfloat162float(hi));
        int q  = c >> 4, cl = c & 15;
        int chunk = q*KK + k;
        g_wq[((chunk*2 + 0)*OCC + oc)*24 + cl] = hi;
        g_wq[((chunk*2 + 1)*OCC + oc)*24 + cl] = lo;
    }

    __shared__ __align__(16) float sA[CC*9*12];   // [(c*9 + t)*12 + k] 27648 B
    __shared__ float sP[3][128*13];               // partials, stride 13  19968 B
    for (int i = tid; i < CC*9*KK; i += 512) {
        int c = i / 81, rem = i % 81, t = rem / 9, k = rem % 9;
        sA[(c*9 + t)*12 + k] = ow[(k*CC + c)*9 + t];
    }
    __syncthreads();

    int px = tid & 127;
    int slice = tid >> 7;            // 0..3, channels [slice*16, slice*16+16)
    int gidx = blockIdx.x * 128 + px;
    int h = gidx % HH;
    int w = (gidx / HH) % WW;
    int b = gidx / (WW*HH);

    float acc[KK];
    #pragma unroll
    for (int k = 0; k < KK; k++) acc[k] = 0.f;

    const float* fb = f + b*CC*WH;
    int c0 = slice * 16;
    #pragma unroll
    for (int r = 0; r < 3; r++) {
        int y = w + r - 1;
        if ((unsigned)y >= (unsigned)WW) continue;
        #pragma unroll
        for (int s = 0; s < 3; s++) {
            int x = h + s - 1;
            if ((unsigned)x >= (unsigned)HH) continue;
            int t = r*3 + s;
            const float* fp = fb + (size_t)c0*WH + y*HH + x;
            #pragma unroll 4
            for (int cc = 0; cc < 16; cc++) {
                float v = __ldg(fp + cc*WH);
                const float4* wp = (const float4*)&sA[((c0+cc)*9 + t)*12];
                float4 q0 = wp[0], q1 = wp[1];
                float  w8 = sA[((c0+cc)*9 + t)*12 + 8];
                acc[0] += v * q0.x;  acc[1] += v * q0.y;
                acc[2] += v * q0.z;  acc[3] += v * q0.w;
                acc[4] += v * q1.x;  acc[5] += v * q1.y;
                acc[6] += v * q1.z;  acc[7] += v * q1.w;
                acc[8] += v * w8;
            }
        }
    }

    if (slice > 0) {
        #pragma unroll
        for (int k = 0; k < KK; k++) sP[slice-1][px*13 + k] = acc[k];
    }
    __syncthreads();
    if (slice > 0) return;

    #pragma unroll
    for (int k = 0; k < KK; k++)
        acc[k] += sP[0][px*13 + k] + sP[1][px*13 + k] + sP[2][px*13 + k];

    float offs[KK];
    #pragma unroll
    for (int k = 0; k < KK; k++) {
        float sc  = rsqrtf(__ldg(bn_v + k) + EPSF);
        float val = (acc[k] + __ldg(ob + k) - __ldg(bn_m + k)) * sc;
        val = val * __ldg(bn_g + k) + __ldg(bn_b + k);
        offs[k] = tanhf(val);
    }

    // center-out cumsum; endpoints k=0, k=8 stay RAW (reference quirk)
    float nw[KK];
    nw[4] = 0.f;
    nw[5] = offs[5];  nw[6] = nw[5] + offs[6];  nw[7] = nw[6] + offs[7];
    nw[3] = offs[3];  nw[2] = nw[3] + offs[2];  nw[1] = nw[2] + offs[1];
    nw[0] = offs[0];
    nw[8] = offs[8];

    #pragma unroll
    for (int k = 0; k < KK; k++)
        g_y[((b*KK + k)*WW + w)*HH + h] = (float)w + nw[k];
}

// ---------------------------------------------------------------------------
// Kernel B: per (b,w) CTA, D[128h x 64oc] = sum_k G_k[128x64c] . W_k^T.
// (R9-measured version: staged-row gather, serial per-phase structure.)
// ---------------------------------------------------------------------------
__global__ void __launch_bounds__(256, 2) dsconv_mma_kernel(
    const float* __restrict__ f,
    const float* __restrict__ cb)
{
    extern __shared__ char smem[];
    float* SFp = (float*)smem;
    uint32_t sb = smem_u32(smem);
    int tid  = threadIdx.x;
    int lane = tid & 31;
    int wid  = tid >> 5;
    int w = blockIdx.x, b = blockIdx.y;

    int mrow = (wid & 3) * 32;
    int ncol = (wid >> 2) * 32;

    int h   = tid & 127;
    int sub = tid >> 7;

    float d[2][4][4];
    #pragma unroll
    for (int mt = 0; mt < 2; mt++)
        #pragma unroll
        for (int nt = 0; nt < 4; nt++)
            #pragma unroll
            for (int r = 0; r < 4; r++) d[mt][nt][r] = 0.f;

    float ysr[KK];
    #pragma unroll
    for (int k = 0; k < KK; k++)
        ysr[k] = g_y[((b*KK + k)*WW + w)*HH + h];

    const float* fb = f + b*CC*WH;

    uint32_t a_roff = (uint32_t)(lane & 15) * 48 + ((lane & 16) ? 16u : 0u);
    uint32_t b_roff = ((uint32_t)(lane & 7) + ((lane & 16) ? 8u : 0u)) * 48
                    + ((lane & 8) ? 16u : 0u);

    int phase = 0;
    for (int q = 0; q < 4; q++) {
        // ---- stage 16 channels x 7 rows x 128 x (float4 coalesced) ----
        {
            const float* fq = fb + (q*16)*WH;
            #pragma unroll
            for (int j = 0; j < 14; j++) {
                int idx  = tid + j*256;
                int cl   = idx / 224;
                int rem  = idx % 224;
                int slot = rem >> 5;
                int x4   = rem & 31;
                int row  = w - 3 + slot;
                row = max(0, min(row, WW-1));
                float4 v = __ldg((const float4*)(fq + cl*WH + row*HH) + x4);
                *((float4*)(SFp + (cl*7 + slot)*128) + x4) = v;
            }
        }
        __syncthreads();

        for (int k = 0; k < KK; k++) {
            int buf = phase & 1;

            // ---- B chunk via cp.async (hi+lo contiguous, 6144 B) ----
            {
                const char* src = (const char*)g_wq + (q*KK + k)*6144;
                uint32_t dst = sb + SB_OFF + buf*6144;
                #pragma unroll
                for (int i = 0; i < 2; i++) {
                    int t = tid + i*256;
                    if (t < 384) CP_ASYNC16(dst + t*16, src + t*16);
                }
                CP_COMMIT();
            }

            // ---- bilinear gather from staged rows (LDS, conflict-free) ----
            float ys = ysr[k];
            float xs = (float)h + c_lin[k];
            int y0 = (int)floorf(ys); y0 = max(0, min(y0, WW-1));
            int y1 = min(y0 + 1, WW-1);
            int x0 = (int)floorf(xs); x0 = max(0, min(x0, HH-1));
            int x1 = min(x0 + 1, HH-1);
            float wy0 = ys - (float)y0, wy1 = (float)y1 - ys;
            float wx0 = xs - (float)x0, wx1 = (float)x1 - xs;
            float w00 = wy1*wx1, w01 = wy1*wx0, w10 = wy0*wx1, w11 = wy0*wx0;

            int s00 = (y0 - (w-3))*128 + x0;
            int s01 = s00 + (x1 - x0);
            int s10 = (y1 - (w-3))*128 + x0;
            int s11 = s10 + (x1 - x0);

            const float* base = SFp + (sub*8)*7*128;
            uint32_t hp[4], lp[4];
            #pragma unroll
            for (int j = 0; j < 4; j++) {
                float sA0, sB0;
                {
                    float a00 = base[s00], a01 = base[s01];
                    float a10 = base[s10], a11 = base[s11];
                    sA0 = w00*a00 + w01*a01 + w10*a10 + w11*a11;
                    base += 896;
                    float b00 = base[s00], b01 = base[s01];
                    float b10 = base[s10], b11 = base[s11];
                    sB0 = w00*b00 + w01*b01 + w10*b10 + w11*b11;
                    base += 896;
                }
                __nv_bfloat16 h0 = __float2bfloat16(sA0);
                __nv_bfloat16 h1 = __float2bfloat16(sB0);
                __nv_bfloat16 l0 = __float2bfloat16(sA0 - __bfloat162float(h0));
                __nv_bfloat16 l1 = __float2bfloat16(sB0 - __bfloat162float(h1));
                hp[j] = (uint32_t)__bfloat16_as_ushort(h0)
                      | ((uint32_t)__bfloat16_as_ushort(h1) << 16);
                lp[j] = (uint32_t)__bfloat16_as_ushort(l0)
                      | ((uint32_t)__bfloat16_as_ushort(l1) << 16);
            }
            {
                char* Abase = smem + SA_OFF + buf*12288;
                *(uint4*)(Abase + h*48 + sub*16)
                    = make_uint4(hp[0], hp[1], hp[2], hp[3]);
                *(uint4*)(Abase + 6144 + h*48 + sub*16)
                    = make_uint4(lp[0], lp[1], lp[2], lp[3]);
            }

            CP_WAIT0();
            __syncthreads();

            // ---- HMMA: one K=16 chunk, hi/lo split (3 products) ----
            uint32_t abase = sb + SA_OFF + buf*12288;
            uint32_t bbase = sb + SB_OFF + buf*6144;

            uint32_t ah[2][4], al[2][4];
            #pragma unroll
            for (int mt = 0; mt < 2; mt++) {
                uint32_t ad = abase + (uint32_t)(mrow + mt*16)*48 + a_roff;
                LDSM_X4(ah[mt][0], ah[mt][1], ah[mt][2], ah[mt][3], ad);
                ad += 6144u;
                LDSM_X4(al[mt][0], al[mt][1], al[mt][2], al[mt][3], ad);
            }
            uint32_t bh[4][2], bl[4][2];
            #pragma unroll
            for (int half = 0; half < 2; half++) {
                uint32_t bd = bbase + (uint32_t)(ncol + half*16)*48 + b_roff;
                LDSM_X4(bh[half*2][0], bh[half*2][1],
                        bh[half*2+1][0], bh[half*2+1][1], bd);
                bd += 3072u;
                LDSM_X4(bl[half*2][0], bl[half*2][1],
                        bl[half*2+1][0], bl[half*2+1][1], bd);
            }
            #pragma unroll
            for (int mt = 0; mt < 2; mt++)
                #pragma unroll
                for (int nt = 0; nt < 4; nt++) {
                    MMA16816(d[mt][nt], ah[mt], bh[nt]);
                    MMA16816(d[mt][nt], ah[mt], bl[nt]);
                    MMA16816(d[mt][nt], al[mt], bh[nt]);
                }
            phase++;
        }
        __syncthreads();   // SF rewrite in next q must wait for this q's gathers
    }

    // ---- epilogue: bias + store z + fused GroupNorm partial stats ----
    int hr = lane >> 2;
    int op = (lane & 3) * 2;
    float gs[4], gq[4];
    #pragma unroll
    for (int nt = 0; nt < 4; nt++) { gs[nt] = 0.f; gq[nt] = 0.f; }

    #pragma unroll
    for (int mt = 0; mt < 2; mt++) {
        int hh = mrow + mt*16 + hr;
        #pragma unroll
        for (int nt = 0; nt < 4; nt++) {
            int oc = ncol + nt*8 + op;
            float b0 = __ldg(cb + oc), b1 = __ldg(cb + oc + 1);
            float* z0 = g_z + ((b*OCC + oc  )*WW + w)*HH;
            float* z1 = g_z + ((b*OCC + oc+1)*WW + w)*HH;
            float v0 = d[mt][nt][0] + b0;
            float v1 = d[mt][nt][1] + b1;
            float v2 = d[mt][nt][2] + b0;
            float v3 = d[mt][nt][3] + b1;
            z0[hh]     = v0;
            z1[hh]     = v1;
            z0[hh + 8] = v2;
            z1[hh + 8] = v3;
            gs[nt] += v0 + v1 + v2 + v3;
            gq[nt] += v0*v0 + v1*v1 + v2*v2 + v3*v3;
        }
    }

    #pragma unroll
    for (int nt = 0; nt < 4; nt++) {
        #pragma unroll
        for (int o = 0; o < 4; o++) {
            int m = (o == 0) ? 1 : (o == 1) ? 4 : (o == 2) ? 8 : 16;
            gs[nt] += __shfl_xor_sync(0xffffffffu, gs[nt], m);
            gq[nt] += __shfl_xor_sync(0xffffffffu, gq[nt], m);
        }
    }
    if ((lane & ~2) == 0) {
        int gpar = (lane >> 1) & 1;
        #pragma unroll
        for (int nt = 0; nt < 4; nt++) {
            int grp = b*GG + (ncol >> 2) + nt*2 + gpar;
            atomicAdd(&g_gsum[grp], gs[nt]);
            atomicAdd(&g_gsq [grp], gq[nt]);
        }
    }
}

// ---------------------------------------------------------------------------
// Kernel C: GroupNorm finalize + gamma/beta + ReLU, 2 float4 per thread
// ---------------------------------------------------------------------------
#define GN_HALF (BB*OCC*WH/8)
__global__ void __launch_bounds__(256) gn_kernel(
    const float* __restrict__ gn_g,
    const float* __restrict__ gn_b,
    float* __restrict__ out)
{
    int t = blockIdx.x * 256 + threadIdx.x;
    if (t >= GN_HALF) return;
    #pragma unroll
    for (int rep = 0; rep < 2; rep++) {
        int i4 = t + rep*GN_HALF;
        int base = i4 * 4;
        int oc = (base / WH) % OCC;
        int b  = base / (OCC*WH);
        int grp = b*GG + (oc >> 2);
        const float invn = 1.f / (float)(4*WH);
        float mu  = g_gsum[grp] * invn;
        float var = g_gsq [grp] * invn - mu*mu;
        float rs  = rsqrtf(var + EPSF);
        float sc = rs * __ldg(gn_g + oc);
        float sh = __ldg(gn_b + oc) - mu * sc;
        float4 z = ((const float4*)g_z)[i4];
        float4 o;
        o.x = fmaxf(z.x*sc + sh, 0.f);
        o.y = fmaxf(z.y*sc + sh, 0.f);
        o.z = fmaxf(z.z*sc + sh, 0.f);
        o.w = fmaxf(z.w*sc + sh, 0.f);
        ((float4*)out)[i4] = o;
    }
}

// ---------------------------------------------------------------------------
extern "C" void kernel_launch(void* const* d_in, const int* in_sizes, int n_in,
                              void* d_out, int out_size)
{
    const float* f        = (const float*)d_in[0];
    const float* offset_w = (const float*)d_in[1];
    const float* offset_b = (const float*)d_in[2];
    const float* bn_gamma = (const float*)d_in[3];
    const float* bn_beta  = (const float*)d_in[4];
    const float* bn_mean  = (const float*)d_in[5];
    const float* bn_var   = (const float*)d_in[6];
    const float* conv_w   = (const float*)d_in[7];
    const float* conv_b   = (const float*)d_in[8];
    const float* gn_gamma = (const float*)d_in[9];
    const float* gn_beta  = (const float*)d_in[10];
    float* out = (float*)d_out;

    cudaFuncSetAttribute(dsconv_mma_kernel,
                         cudaFuncAttributeMaxDynamicSharedMemorySize, S_TOT);

    offset_kernel<<<(BB*WW*HH)/128, 512>>>(f, offset_w, offset_b,
                                           bn_gamma, bn_beta, bn_mean, bn_var,
                                           conv_w);

    dim3 gridB(WW, BB);
    dsconv_mma_kernel<<<gridB, 256, S_TOT>>>(f, conv_b);

    gn_kernel<<<(GN_HALF + 255)/256, 256>>>(gn_gamma, gn_beta, out);
}